// round 8
// baseline (speedup 1.0000x reference)
#include <cuda_runtime.h>

#define NNODES 65536
#define NC 256

typedef unsigned long long u64;

// Persistent scratch (no allocations allowed)
__device__ float g_bufA[NNODES * NC];   // xt (NHWC nodes) -> later agg
__device__ float g_bufB[NNODES * NC];   // conv_out -> later g
__device__ float g_nodes[NNODES * NC];  // bn2d+relu node features
__device__ float g_wt[9 * NC * NC];     // conv weights [tap][ci][co]
__device__ float g_wcat[512 * NC];      // [k][co]: k<256 -> w_rel^T, k>=256 -> w_root^T
__device__ float g_stats[1024];         // sum2d, sumsq2d, sum1d, sumsq1d
__device__ float g_coef[1024];          // sc2d, sh2d, sc1d, sh1d
__device__ int   g_is32;                // edge_index dtype flag

__device__ __forceinline__ void fma2(u64& d, u64 a, u64 b) {
    asm("fma.rn.f32x2 %0, %1, %2, %0;" : "+l"(d) : "l"(a), "l"(b));
}
__device__ __forceinline__ void unpack2(u64 v, float& lo, float& hi) {
    asm("mov.b64 {%0, %1}, %2;" : "=f"(lo), "=f"(hi) : "l"(v));
}

// ---------------- transpose x: NCHW -> node-major [node][c] ----------------
__global__ void k_transpose_x(const float* __restrict__ x) {
    __shared__ float tile[256 * 33];
    int bh = blockIdx.x;            // b*32 + h
    int b = bh >> 5, h = bh & 31;
    for (int i = threadIdx.x; i < 8192; i += 256) {
        int c = i >> 5, w = i & 31;
        tile[c * 33 + w] = x[((b * NC + c) * 32 + h) * 32 + w];
    }
    __syncthreads();
    int nb = bh * 32;
    for (int i = threadIdx.x; i < 8192; i += 256) {
        int w = i >> 8, c = i & 255;
        g_bufA[(nb + w) * NC + c] = tile[c * 33 + w];
    }
}

// ---------------- weight prep + stats zero ----------------
__global__ void k_prep(const float* __restrict__ cw,
                       const float* __restrict__ wrel,
                       const float* __restrict__ wroot) {
    int i = blockIdx.x * 256 + threadIdx.x;
    if (i < 9 * NC * NC) {
        int tap = i % 9;
        int t = i / 9;
        int ci = t % NC, co = t / NC;
        g_wt[(tap * NC + ci) * NC + co] = cw[i];
    }
    if (i < 512 * NC) {
        int k = i >> 8, co = i & 255;
        g_wcat[i] = (k < NC) ? wrel[co * NC + k] : wroot[co * NC + (k - NC)];
    }
    if (blockIdx.x == 0) {
        for (int j = threadIdx.x; j < 1024; j += 256) g_stats[j] = 0.f;
    }
}

// ---------------- edge dtype detection (single block -> no race) ----------------
__global__ void k_detect(const int* __restrict__ ei32) {
    __shared__ int any;
    if (threadIdx.x == 0) any = 0;
    __syncthreads();
    int a = 0;
    for (int j = threadIdx.x; j < 8192; j += 256) a |= ei32[2 * j + 1];
    if (a) atomicOr(&any, 1);
    __syncthreads();
    if (threadIdx.x == 0) g_is32 = (any != 0) ? 1 : 0;
}

// ---------------- conv 3x3 as implicit GEMM (k-paired f32x2) ----------------
// Tile: 64 M x 128 N, 256 threads, 2 CTAs/SM.
// As[m][k] 64x36 pad; Bsp[k2][n] u64 = {B[2k2][n], B[2k2+1][n]}, row stride 260 fl.
__global__ __launch_bounds__(256, 2) void k_conv(const float* __restrict__ bias) {
    __shared__ float As[64 * 36];
    __shared__ float Bsp[16 * 260];
    int mbase = blockIdx.x * 64;
    int nbase = blockIdx.y * 128;
    int tid = threadIdx.x;
    int tx = tid & 31, ty = tid >> 5;
    int m0 = ty * 8;
    u64 acc[8][4] = {};   // [m][{2tx,2tx+1,2tx+64,2tx+65}]

    for (int tap = 0; tap < 9; tap++) {
        int dy = tap / 3 - 1, dx = tap % 3 - 1;
        int nofs = dy * 32 + dx;
        for (int kc = 0; kc < 8; kc++) {
            // A fill: 2 float4 per thread
            #pragma unroll
            for (int i = 0; i < 2; i++) {
                int s = tid + i * 256;
                int m = s >> 3, cq = s & 7;
                int node = mbase + m;
                int hh = ((node >> 5) & 31) + dy;
                int ww = (node & 31) + dx;
                float4 v = make_float4(0.f, 0.f, 0.f, 0.f);
                if ((unsigned)hh < 32u && (unsigned)ww < 32u)
                    v = *(const float4*)&g_bufA[(node + nofs) * NC + kc * 32 + cq * 4];
                *(float4*)&As[m * 36 + cq * 4] = v;
            }
            // B fill: interleave k-pairs; 4 slots of 2 n per thread
            const float* wrow = &g_wt[(tap * NC + kc * 32) * NC + nbase];
            #pragma unroll
            for (int i = 0; i < 4; i++) {
                int s = tid + i * 256;
                int n4 = s & 63, k2 = s >> 6;
                float2 r0 = *(const float2*)&wrow[(2 * k2) * NC + 2 * n4];
                float2 r1 = *(const float2*)&wrow[(2 * k2 + 1) * NC + 2 * n4];
                *(float4*)&Bsp[k2 * 260 + 4 * n4] = make_float4(r0.x, r1.x, r0.y, r1.y);
            }
            __syncthreads();
            #pragma unroll 4
            for (int kk2 = 0; kk2 < 16; kk2++) {
                ulonglong2 bA = *(const ulonglong2*)&Bsp[kk2 * 260 + 4 * tx];
                ulonglong2 bB = *(const ulonglong2*)&Bsp[kk2 * 260 + 4 * tx + 128];
                const float* ar = &As[m0 * 36 + 2 * kk2];
                #pragma unroll
                for (int i = 0; i < 8; i++) {
                    u64 a = *(const u64*)&ar[i * 36];
                    fma2(acc[i][0], a, bA.x);
                    fma2(acc[i][1], a, bA.y);
                    fma2(acc[i][2], a, bB.x);
                    fma2(acc[i][3], a, bB.y);
                }
            }
            __syncthreads();
        }
    }
    float b0 = bias[nbase + 2 * tx], b1 = bias[nbase + 2 * tx + 1];
    float b2 = bias[nbase + 2 * tx + 64], b3 = bias[nbase + 2 * tx + 65];
    #pragma unroll
    for (int i = 0; i < 8; i++) {
        int row = mbase + m0 + i;
        float lo, hi, r0, r1, r2, r3;
        unpack2(acc[i][0], lo, hi); r0 = lo + hi + b0;
        unpack2(acc[i][1], lo, hi); r1 = lo + hi + b1;
        unpack2(acc[i][2], lo, hi); r2 = lo + hi + b2;
        unpack2(acc[i][3], lo, hi); r3 = lo + hi + b3;
        *(float2*)&g_bufB[row * NC + nbase + 2 * tx] = make_float2(r0, r1);
        *(float2*)&g_bufB[row * NC + nbase + 2 * tx + 64] = make_float2(r2, r3);
    }
}

// ---------------- per-channel sum/sumsq over g_bufB ----------------
__global__ void k_stats(int so) {
    int c = threadIdx.x;
    int r0 = blockIdx.x * 64;
    float s = 0.f, ss = 0.f;
    #pragma unroll 4
    for (int r = 0; r < 64; r++) {
        float v = g_bufB[(r0 + r) * NC + c];
        s += v;
        ss += v * v;
    }
    atomicAdd(&g_stats[so + c], s);
    atomicAdd(&g_stats[so + 256 + c], ss);
}

__global__ void k_coef(int so, const float* __restrict__ gamma,
                       const float* __restrict__ beta, int co) {
    int c = threadIdx.x;
    float mean = g_stats[so + c] * (1.f / NNODES);
    float var  = g_stats[so + 256 + c] * (1.f / NNODES) - mean * mean;
    float sc = gamma[c] * rsqrtf(var + 1e-5f);
    g_coef[co + c] = sc;
    g_coef[co + 256 + c] = beta[c] - mean * sc;
}

// ---------------- bn2d+relu -> nodes ; zero agg ----------------
__global__ void k_bnrelu_zero() {
    int idx = blockIdx.x * 256 + threadIdx.x;  // float4 index, 4194304 total
    int c4 = idx & 63;
    float4 v  = ((const float4*)g_bufB)[idx];
    float4 sc = ((const float4*)g_coef)[c4];
    float4 sh = ((const float4*)(g_coef + 256))[c4];
    v.x = fmaxf(fmaf(v.x, sc.x, sh.x), 0.f);
    v.y = fmaxf(fmaf(v.y, sc.y, sh.y), 0.f);
    v.z = fmaxf(fmaf(v.z, sc.z, sh.z), 0.f);
    v.w = fmaxf(fmaf(v.w, sc.w, sh.w), 0.f);
    ((float4*)g_nodes)[idx] = v;
    ((float4*)g_bufA)[idx] = make_float4(0.f, 0.f, 0.f, 0.f);
}

// ---------------- edge scatter-add: agg[dst] += nodes[src] ----------------
__global__ void k_scatter(const void* __restrict__ ei, int E) {
    int e = blockIdx.x * 8 + (threadIdx.x >> 5);
    if (e >= E) return;
    int lane = threadIdx.x & 31;
    int src, dst;
    if (g_is32) {
        const int* p = (const int*)ei;
        src = p[e]; dst = p[E + e];
    } else {
        const long long* p = (const long long*)ei;
        src = (int)p[e]; dst = (int)p[E + e];
    }
    const float4* sp = (const float4*)&g_nodes[src * NC];
    float4* dp = (float4*)&g_bufA[dst * NC];
    #pragma unroll
    for (int i = 0; i < 2; i++) {
        float4 v = sp[lane + i * 32];
        float4* p4 = dp + lane + i * 32;
        asm volatile("red.global.add.v4.f32 [%0], {%1,%2,%3,%4};"
                     :: "l"(p4), "f"(v.x), "f"(v.y), "f"(v.z), "f"(v.w)
                     : "memory");
    }
}

// ---------------- graph GEMM: g = [agg|nodes] @ wcat + b_rel (k-paired f32x2)
__global__ __launch_bounds__(256, 2) void k_gemm(const float* __restrict__ brel) {
    __shared__ float As[64 * 36];
    __shared__ float Bsp[16 * 260];
    int mbase = blockIdx.x * 64;
    int nbase = blockIdx.y * 128;
    int tid = threadIdx.x;
    int tx = tid & 31, ty = tid >> 5;
    int m0 = ty * 8;
    u64 acc[8][4] = {};

    for (int kc = 0; kc < 16; kc++) {
        const float* src = (kc < 8) ? g_bufA : g_nodes;
        int coff = (kc & 7) * 32;
        #pragma unroll
        for (int i = 0; i < 2; i++) {
            int s = tid + i * 256;
            int m = s >> 3, cq = s & 7;
            *(float4*)&As[m * 36 + cq * 4] =
                *(const float4*)&src[(mbase + m) * NC + coff + cq * 4];
        }
        const float* wrow = &g_wcat[(kc * 32) * NC + nbase];
        #pragma unroll
        for (int i = 0; i < 4; i++) {
            int s = tid + i * 256;
            int n4 = s & 63, k2 = s >> 6;
            float2 r0 = *(const float2*)&wrow[(2 * k2) * NC + 2 * n4];
            float2 r1 = *(const float2*)&wrow[(2 * k2 + 1) * NC + 2 * n4];
            *(float4*)&Bsp[k2 * 260 + 4 * n4] = make_float4(r0.x, r1.x, r0.y, r1.y);
        }
        __syncthreads();
        #pragma unroll 4
        for (int kk2 = 0; kk2 < 16; kk2++) {
            ulonglong2 bA = *(const ulonglong2*)&Bsp[kk2 * 260 + 4 * tx];
            ulonglong2 bB = *(const ulonglong2*)&Bsp[kk2 * 260 + 4 * tx + 128];
            const float* ar = &As[m0 * 36 + 2 * kk2];
            #pragma unroll
            for (int i = 0; i < 8; i++) {
                u64 a = *(const u64*)&ar[i * 36];
                fma2(acc[i][0], a, bA.x);
                fma2(acc[i][1], a, bA.y);
                fma2(acc[i][2], a, bB.x);
                fma2(acc[i][3], a, bB.y);
            }
        }
        __syncthreads();
    }
    float b0 = brel[nbase + 2 * tx], b1 = brel[nbase + 2 * tx + 1];
    float b2 = brel[nbase + 2 * tx + 64], b3 = brel[nbase + 2 * tx + 65];
    #pragma unroll
    for (int i = 0; i < 8; i++) {
        int row = mbase + m0 + i;
        float lo, hi, r0, r1, r2, r3;
        unpack2(acc[i][0], lo, hi); r0 = lo + hi + b0;
        unpack2(acc[i][1], lo, hi); r1 = lo + hi + b1;
        unpack2(acc[i][2], lo, hi); r2 = lo + hi + b2;
        unpack2(acc[i][3], lo, hi); r3 = lo + hi + b3;
        *(float2*)&g_bufB[row * NC + nbase + 2 * tx] = make_float2(r0, r1);
        *(float2*)&g_bufB[row * NC + nbase + 2 * tx + 64] = make_float2(r2, r3);
    }
}

// ---------------- bn1d+relu, transpose back to NCHW, residual ----------------
__global__ void k_final(const float* __restrict__ x, float* __restrict__ out) {
    __shared__ float tile[32 * 257];
    int bh = blockIdx.x;
    int b = bh >> 5, h = bh & 31;
    int nb = bh * 32;
    for (int i = threadIdx.x; i < 8192; i += 256) {
        int w = i >> 8, c = i & 255;
        tile[w * 257 + c] = g_bufB[(nb + w) * NC + c];
    }
    __syncthreads();
    for (int i = threadIdx.x; i < 8192; i += 256) {
        int c = i >> 5, w = i & 31;
        float v = fmaf(tile[w * 257 + c], g_coef[512 + c], g_coef[768 + c]);
        v = fmaxf(v, 0.f);
        int o = ((b * NC + c) * 32 + h) * 32 + w;
        out[o] = v + x[o];
    }
}

extern "C" void kernel_launch(void* const* d_in, const int* in_sizes, int n_in,
                              void* d_out, int out_size) {
    const float* x      = (const float*)d_in[0];
    const void*  ei     = d_in[1];
    const float* conv_w = (const float*)d_in[2];
    const float* conv_b = (const float*)d_in[3];
    const float* bn2d_g = (const float*)d_in[4];
    const float* bn2d_b = (const float*)d_in[5];
    const float* w_rel  = (const float*)d_in[6];
    const float* b_rel  = (const float*)d_in[7];
    const float* w_root = (const float*)d_in[8];
    const float* bn1d_g = (const float*)d_in[9];
    const float* bn1d_b = (const float*)d_in[10];
    float* out = (float*)d_out;
    int E = in_sizes[1] / 2;

    k_transpose_x<<<2048, 256>>>(x);
    k_prep<<<2304, 256>>>(conv_w, w_rel, w_root);
    k_detect<<<1, 256>>>((const int*)ei);
    k_conv<<<dim3(1024, 2), 256>>>(conv_b);
    k_stats<<<1024, 256>>>(0);
    k_coef<<<1, 256>>>(0, bn2d_g, bn2d_b, 0);
    k_bnrelu_zero<<<16384, 256>>>();
    k_scatter<<<(E + 7) / 8, 256>>>(ei, E);
    k_gemm<<<dim3(1024, 2), 256>>>(b_rel);
    k_stats<<<1024, 256>>>(512);
    k_coef<<<1, 256>>>(512, bn1d_g, bn1d_b, 512);
    k_final<<<2048, 256>>>(x, out);
}

// round 10
// speedup vs baseline: 1.4230x; 1.4230x over previous
#include <cuda_runtime.h>
#include <cstdint>

#define NNODES 65536
#define NC 256

typedef unsigned long long u64;

// Persistent scratch (no allocations allowed)
__device__ float g_bufA[NNODES * NC];   // xt (NHWC nodes) -> later agg
__device__ float g_bufB[NNODES * NC];   // conv_out -> later g
__device__ float g_nodes[NNODES * NC];  // bn2d+relu node features
__device__ float g_wt[9 * NC * NC];     // conv weights K-major: [tap][co][ci]
__device__ float g_stats[1024];         // sum2d, sumsq2d, sum1d, sumsq1d
__device__ float g_coef[1024];          // sc2d, sh2d, sc1d, sh1d
__device__ int   g_is32;                // edge_index dtype flag

__device__ __forceinline__ uint32_t f2tf(float f) {
    uint32_t r;
    asm("cvt.rna.tf32.f32 %0, %1;" : "=r"(r) : "f"(f));
    return r;
}
__device__ __forceinline__ void mma8(float* c, const uint32_t* a, const uint32_t* b) {
    asm volatile(
        "mma.sync.aligned.m16n8k8.row.col.f32.tf32.tf32.f32 "
        "{%0,%1,%2,%3}, {%4,%5,%6,%7}, {%8,%9}, {%0,%1,%2,%3};"
        : "+f"(c[0]), "+f"(c[1]), "+f"(c[2]), "+f"(c[3])
        : "r"(a[0]), "r"(a[1]), "r"(a[2]), "r"(a[3]), "r"(b[0]), "r"(b[1]));
}

// ---------------- transpose x: NCHW -> node-major [node][c] ----------------
__global__ void k_transpose_x(const float* __restrict__ x) {
    __shared__ float tile[256 * 33];
    int bh = blockIdx.x;
    int b = bh >> 5, h = bh & 31;
    for (int i = threadIdx.x; i < 8192; i += 256) {
        int c = i >> 5, w = i & 31;
        tile[c * 33 + w] = x[((b * NC + c) * 32 + h) * 32 + w];
    }
    __syncthreads();
    int nb = bh * 32;
    for (int i = threadIdx.x; i < 8192; i += 256) {
        int w = i >> 8, c = i & 255;
        g_bufA[(nb + w) * NC + c] = tile[c * 33 + w];
    }
}

// ---------------- weight prep (K-major) + stats zero ----------------
__global__ void k_prep(const float* __restrict__ cw) {
    int i = blockIdx.x * 256 + threadIdx.x;
    if (i < 9 * NC * NC) {
        int tap = i % 9;
        int t = i / 9;
        int ci = t % NC, co = t / NC;
        g_wt[(tap * NC + co) * NC + ci] = cw[i];
    }
    if (blockIdx.x == 0) {
        for (int j = threadIdx.x; j < 1024; j += 256) g_stats[j] = 0.f;
    }
}

// ---------------- edge dtype detection ----------------
__global__ void k_detect(const int* __restrict__ ei32) {
    __shared__ int any;
    if (threadIdx.x == 0) any = 0;
    __syncthreads();
    int a = 0;
    for (int j = threadIdx.x; j < 8192; j += 256) a |= ei32[2 * j + 1];
    if (a) atomicOr(&any, 1);
    __syncthreads();
    if (threadIdx.x == 0) g_is32 = (any != 0) ? 1 : 0;
}

// ---------------- conv 3x3: implicit GEMM on mma.sync tf32 ----------------
// 128M x 128N tile, K-chunks of 32. 8 warps (2m x 4n), warp tile 64x32.
__global__ __launch_bounds__(256, 2) void k_conv(const float* __restrict__ bias) {
    __shared__ uint32_t As[128 * 36];
    __shared__ uint32_t Bs[128 * 36];
    int tid = threadIdx.x;
    int wid = tid >> 5, lane = tid & 31;
    int mbase = blockIdx.x * 128, nbase = blockIdx.y * 128;
    int wm0 = (wid >> 2) * 64, wn0 = (wid & 3) * 32;
    int gA = lane >> 2, cA = lane & 3;
    int r = tid >> 1, h = tid & 1;
    float c[4][4][4] = {};

    for (int tap = 0; tap < 9; tap++) {
        int dy = tap / 3 - 1, dx = tap % 3 - 1;
        int nofs = dy * 32 + dx;
        for (int kc = 0; kc < 8; kc++) {
            int node = mbase + r;
            int hh = ((node >> 5) & 31) + dy;
            int ww = (node & 31) + dx;
            bool ok = ((unsigned)hh < 32u) && ((unsigned)ww < 32u);
            const float4* asrc = (const float4*)&g_bufA[(node + nofs) * NC + kc * 32 + h * 16];
            const float4* bsrc = (const float4*)&g_wt[(tap * NC + nbase + r) * NC + kc * 32 + h * 16];
            #pragma unroll
            for (int j = 0; j < 4; j++) {
                float4 va = ok ? asrc[j] : make_float4(0.f, 0.f, 0.f, 0.f);
                float4 vb = bsrc[j];
                uint32_t* da = &As[r * 36 + h * 16 + j * 4];
                uint32_t* db = &Bs[r * 36 + h * 16 + j * 4];
                da[0] = f2tf(va.x); da[1] = f2tf(va.y); da[2] = f2tf(va.z); da[3] = f2tf(va.w);
                db[0] = f2tf(vb.x); db[1] = f2tf(vb.y); db[2] = f2tf(vb.z); db[3] = f2tf(vb.w);
            }
            __syncthreads();
            #pragma unroll
            for (int ks = 0; ks < 4; ks++) {
                int k0 = ks * 8;
                uint32_t a[4][4], b[4][2];
                #pragma unroll
                for (int mt = 0; mt < 4; mt++) {
                    int row = (wm0 + mt * 16 + gA) * 36 + k0 + cA;
                    a[mt][0] = As[row];
                    a[mt][1] = As[row + 8 * 36];
                    a[mt][2] = As[row + 4];
                    a[mt][3] = As[row + 8 * 36 + 4];
                }
                #pragma unroll
                for (int nt = 0; nt < 4; nt++) {
                    int row = (wn0 + nt * 8 + gA) * 36 + k0 + cA;
                    b[nt][0] = Bs[row];
                    b[nt][1] = Bs[row + 4];
                }
                #pragma unroll
                for (int mt = 0; mt < 4; mt++)
                    #pragma unroll
                    for (int nt = 0; nt < 4; nt++)
                        mma8(c[mt][nt], a[mt], b[nt]);
            }
            __syncthreads();
        }
    }
    #pragma unroll
    for (int mt = 0; mt < 4; mt++) {
        #pragma unroll
        for (int nt = 0; nt < 4; nt++) {
            int row = mbase + wm0 + mt * 16 + gA;
            int col = nbase + wn0 + nt * 8 + 2 * cA;
            float b0 = bias[col], b1 = bias[col + 1];
            *(float2*)&g_bufB[row * NC + col] =
                make_float2(c[mt][nt][0] + b0, c[mt][nt][1] + b1);
            *(float2*)&g_bufB[(row + 8) * NC + col] =
                make_float2(c[mt][nt][2] + b0, c[mt][nt][3] + b1);
        }
    }
}

// ---------------- per-channel sum/sumsq over g_bufB ----------------
__global__ void k_stats(int so) {
    int c = threadIdx.x;
    int r0 = blockIdx.x * 64;
    float s = 0.f, ss = 0.f;
    #pragma unroll 4
    for (int r = 0; r < 64; r++) {
        float v = g_bufB[(r0 + r) * NC + c];
        s += v;
        ss += v * v;
    }
    atomicAdd(&g_stats[so + c], s);
    atomicAdd(&g_stats[so + 256 + c], ss);
}

__global__ void k_coef(int so, const float* __restrict__ gamma,
                       const float* __restrict__ beta, int co) {
    int c = threadIdx.x;
    float mean = g_stats[so + c] * (1.f / NNODES);
    float var  = g_stats[so + 256 + c] * (1.f / NNODES) - mean * mean;
    float sc = gamma[c] * rsqrtf(var + 1e-5f);
    g_coef[co + c] = sc;
    g_coef[co + 256 + c] = beta[c] - mean * sc;
}

// ---------------- bn2d+relu -> nodes ; zero agg ----------------
__global__ void k_bnrelu_zero() {
    int idx = blockIdx.x * 256 + threadIdx.x;
    int c4 = idx & 63;
    float4 v  = ((const float4*)g_bufB)[idx];
    float4 sc = ((const float4*)g_coef)[c4];
    float4 sh = ((const float4*)(g_coef + 256))[c4];
    v.x = fmaxf(fmaf(v.x, sc.x, sh.x), 0.f);
    v.y = fmaxf(fmaf(v.y, sc.y, sh.y), 0.f);
    v.z = fmaxf(fmaf(v.z, sc.z, sh.z), 0.f);
    v.w = fmaxf(fmaf(v.w, sc.w, sh.w), 0.f);
    ((float4*)g_nodes)[idx] = v;
    ((float4*)g_bufA)[idx] = make_float4(0.f, 0.f, 0.f, 0.f);
}

// ---------------- edge scatter-add: agg[dst] += nodes[src] ----------------
__global__ void k_scatter(const void* __restrict__ ei, int E) {
    int e = blockIdx.x * 8 + (threadIdx.x >> 5);
    if (e >= E) return;
    int lane = threadIdx.x & 31;
    int src, dst;
    if (g_is32) {
        const int* p = (const int*)ei;
        src = p[e]; dst = p[E + e];
    } else {
        const long long* p = (const long long*)ei;
        src = (int)p[e]; dst = (int)p[E + e];
    }
    const float4* sp = (const float4*)&g_nodes[src * NC];
    float4* dp = (float4*)&g_bufA[dst * NC];
    #pragma unroll
    for (int i = 0; i < 2; i++) {
        float4 v = sp[lane + i * 32];
        float4* p4 = dp + lane + i * 32;
        asm volatile("red.global.add.v4.f32 [%0], {%1,%2,%3,%4};"
                     :: "l"(p4), "f"(v.x), "f"(v.y), "f"(v.z), "f"(v.w)
                     : "memory");
    }
}

// ---------------- graph GEMM: g = [agg|nodes] @ [wrel|wroot]^T + b_rel ------
__global__ __launch_bounds__(256, 2) void k_gemm(const float* __restrict__ wrel,
                                                 const float* __restrict__ wroot,
                                                 const float* __restrict__ brel) {
    __shared__ uint32_t As[128 * 36];
    __shared__ uint32_t Bs[128 * 36];
    int tid = threadIdx.x;
    int wid = tid >> 5, lane = tid & 31;
    int mbase = blockIdx.x * 128, nbase = blockIdx.y * 128;
    int wm0 = (wid >> 2) * 64, wn0 = (wid & 3) * 32;
    int gA = lane >> 2, cA = lane & 3;
    int r = tid >> 1, h = tid & 1;
    float c[4][4][4] = {};

    for (int kc = 0; kc < 16; kc++) {
        const float* ab = (kc < 8) ? g_bufA : g_nodes;
        const float* bb = (kc < 8) ? wrel : wroot;
        int coff = (kc & 7) * 32;
        const float4* asrc = (const float4*)&ab[(mbase + r) * NC + coff + h * 16];
        const float4* bsrc = (const float4*)&bb[(nbase + r) * NC + coff + h * 16];
        #pragma unroll
        for (int j = 0; j < 4; j++) {
            float4 va = asrc[j];
            float4 vb = bsrc[j];
            uint32_t* da = &As[r * 36 + h * 16 + j * 4];
            uint32_t* db = &Bs[r * 36 + h * 16 + j * 4];
            da[0] = f2tf(va.x); da[1] = f2tf(va.y); da[2] = f2tf(va.z); da[3] = f2tf(va.w);
            db[0] = f2tf(vb.x); db[1] = f2tf(vb.y); db[2] = f2tf(vb.z); db[3] = f2tf(vb.w);
        }
        __syncthreads();
        #pragma unroll
        for (int ks = 0; ks < 4; ks++) {
            int k0 = ks * 8;
            uint32_t a[4][4], b[4][2];
            #pragma unroll
            for (int mt = 0; mt < 4; mt++) {
                int row = (wm0 + mt * 16 + gA) * 36 + k0 + cA;
                a[mt][0] = As[row];
                a[mt][1] = As[row + 8 * 36];
                a[mt][2] = As[row + 4];
                a[mt][3] = As[row + 8 * 36 + 4];
            }
            #pragma unroll
            for (int nt = 0; nt < 4; nt++) {
                int row = (wn0 + nt * 8 + gA) * 36 + k0 + cA;
                b[nt][0] = Bs[row];
                b[nt][1] = Bs[row + 4];
            }
            #pragma unroll
            for (int mt = 0; mt < 4; mt++)
                #pragma unroll
                for (int nt = 0; nt < 4; nt++)
                    mma8(c[mt][nt], a[mt], b[nt]);
        }
        __syncthreads();
    }
    #pragma unroll
    for (int mt = 0; mt < 4; mt++) {
        #pragma unroll
        for (int nt = 0; nt < 4; nt++) {
            int row = mbase + wm0 + mt * 16 + gA;
            int col = nbase + wn0 + nt * 8 + 2 * cA;
            float b0 = brel[col], b1 = brel[col + 1];
            *(float2*)&g_bufB[row * NC + col] =
                make_float2(c[mt][nt][0] + b0, c[mt][nt][1] + b1);
            *(float2*)&g_bufB[(row + 8) * NC + col] =
                make_float2(c[mt][nt][2] + b0, c[mt][nt][3] + b1);
        }
    }
}

// ---------------- bn1d+relu, transpose back to NCHW, residual ----------------
__global__ void k_final(const float* __restrict__ x, float* __restrict__ out) {
    __shared__ float tile[32 * 257];
    int bh = blockIdx.x;
    int b = bh >> 5, h = bh & 31;
    int nb = bh * 32;
    for (int i = threadIdx.x; i < 8192; i += 256) {
        int w = i >> 8, c = i & 255;
        tile[w * 257 + c] = g_bufB[(nb + w) * NC + c];
    }
    __syncthreads();
    for (int i = threadIdx.x; i < 8192; i += 256) {
        int c = i >> 5, w = i & 31;
        float v = fmaf(tile[w * 257 + c], g_coef[512 + c], g_coef[768 + c]);
        v = fmaxf(v, 0.f);
        int o = ((b * NC + c) * 32 + h) * 32 + w;
        out[o] = v + x[o];
    }
}

extern "C" void kernel_launch(void* const* d_in, const int* in_sizes, int n_in,
                              void* d_out, int out_size) {
    const float* x      = (const float*)d_in[0];
    const void*  ei     = d_in[1];
    const float* conv_w = (const float*)d_in[2];
    const float* conv_b = (const float*)d_in[3];
    const float* bn2d_g = (const float*)d_in[4];
    const float* bn2d_b = (const float*)d_in[5];
    const float* w_rel  = (const float*)d_in[6];
    const float* b_rel  = (const float*)d_in[7];
    const float* w_root = (const float*)d_in[8];
    const float* bn1d_g = (const float*)d_in[9];
    const float* bn1d_b = (const float*)d_in[10];
    float* out = (float*)d_out;
    int E = in_sizes[1] / 2;

    k_transpose_x<<<2048, 256>>>(x);
    k_prep<<<2304, 256>>>(conv_w);
    k_detect<<<1, 256>>>((const int*)ei);
    k_conv<<<dim3(512, 2), 256>>>(conv_b);
    k_stats<<<1024, 256>>>(0);
    k_coef<<<1, 256>>>(0, bn2d_g, bn2d_b, 0);
    k_bnrelu_zero<<<16384, 256>>>();
    k_scatter<<<(E + 7) / 8, 256>>>(ei, E);
    k_gemm<<<dim3(512, 2), 256>>>(w_rel, w_root, b_rel);
    k_stats<<<1024, 256>>>(512);
    k_coef<<<1, 256>>>(512, bn1d_g, bn1d_b, 512);
    k_final<<<2048, 256>>>(x, out);
}

// round 11
// speedup vs baseline: 2.7943x; 1.9637x over previous
#include <cuda_runtime.h>
#include <cuda_fp16.h>
#include <cstdint>

#define NNODES 65536
#define NC 256

typedef unsigned long long u64;

// Persistent scratch (no allocations allowed)
__device__ float g_bufA[NNODES * NC];   // xt (NHWC nodes) -> later agg
__device__ float g_bufB[NNODES * NC];   // conv_out -> later g
__device__ float g_nodes[NNODES * NC];  // bn2d+relu node features
__device__ float g_wt[9 * NC * NC];     // conv weights K-major: [tap][co][ci]
__device__ float g_stats[1024];         // sum2d, sumsq2d, sum1d, sumsq1d
__device__ float g_coef[1024];          // sc2d, sh2d, sc1d, sh1d
__device__ int   g_is32;                // edge_index dtype flag

__device__ __forceinline__ uint32_t h2u(float x, float y) {
    __half2 h = __floats2half2_rn(x, y);
    return *(uint32_t*)&h;
}
__device__ __forceinline__ void mma16(float* c, uint2 alo, uint2 ahi, uint2 b) {
    asm volatile(
        "mma.sync.aligned.m16n8k16.row.col.f32.f16.f16.f32 "
        "{%0,%1,%2,%3}, {%4,%5,%6,%7}, {%8,%9}, {%0,%1,%2,%3};"
        : "+f"(c[0]), "+f"(c[1]), "+f"(c[2]), "+f"(c[3])
        : "r"(alo.x), "r"(ahi.x), "r"(alo.y), "r"(ahi.y), "r"(b.x), "r"(b.y));
}

// Pack one 16-k block (4 float4) into permuted half2 layout:
// u32 slot q holds halves {2q,2q+1} for q even pairs: order U0={k0,k1} U1={k8,k9}
// U2={k2,k3} U3={k10,k11} U4={k4,k5} U5={k12,k13} U6={k6,k7} U7={k14,k15}
// -> LDS.64 at slot 2*cA yields {a0(k=2cA,2cA+1), a2(k=2cA+8,2cA+9)}.
__device__ __forceinline__ void sts_tile(uint32_t* dst, int r, int h,
                                         float4 p0, float4 p1, float4 p2, float4 p3) {
    uint32_t* q = dst + r * 24 + h * 8;
    *(uint4*)q = make_uint4(h2u(p0.x, p0.y), h2u(p2.x, p2.y),
                            h2u(p0.z, p0.w), h2u(p2.z, p2.w));
    *(uint4*)(q + 4) = make_uint4(h2u(p1.x, p1.y), h2u(p3.x, p3.y),
                                  h2u(p1.z, p1.w), h2u(p3.z, p3.w));
}

// ---------------- transpose x: NCHW -> node-major [node][c] ----------------
__global__ void k_transpose_x(const float* __restrict__ x) {
    __shared__ float tile[256 * 33];
    int bh = blockIdx.x;
    int b = bh >> 5, h = bh & 31;
    for (int i = threadIdx.x; i < 8192; i += 256) {
        int c = i >> 5, w = i & 31;
        tile[c * 33 + w] = x[((b * NC + c) * 32 + h) * 32 + w];
    }
    __syncthreads();
    int nb = bh * 32;
    for (int i = threadIdx.x; i < 8192; i += 256) {
        int w = i >> 8, c = i & 255;
        g_bufA[(nb + w) * NC + c] = tile[c * 33 + w];
    }
}

// ---------------- weight prep (K-major) + stats zero ----------------
__global__ void k_prep(const float* __restrict__ cw) {
    int i = blockIdx.x * 256 + threadIdx.x;
    if (i < 9 * NC * NC) {
        int tap = i % 9;
        int t = i / 9;
        int ci = t % NC, co = t / NC;
        g_wt[(tap * NC + co) * NC + ci] = cw[i];
    }
    if (blockIdx.x == 0) {
        for (int j = threadIdx.x; j < 1024; j += 256) g_stats[j] = 0.f;
    }
}

// ---------------- edge dtype detection ----------------
__global__ void k_detect(const int* __restrict__ ei32) {
    __shared__ int any;
    if (threadIdx.x == 0) any = 0;
    __syncthreads();
    int a = 0;
    for (int j = threadIdx.x; j < 8192; j += 256) a |= ei32[2 * j + 1];
    if (a) atomicOr(&any, 1);
    __syncthreads();
    if (threadIdx.x == 0) g_is32 = (any != 0) ? 1 : 0;
}

#define MMA_STEP(SBUF, S)                                                     \
    do {                                                                      \
        uint2 alo[4], ahi[4], bv[4];                                          \
        _Pragma("unroll")                                                     \
        for (int mt = 0; mt < 4; mt++) {                                      \
            int row = wm0 + mt * 16 + gA;                                     \
            alo[mt] = *(const uint2*)&As[SBUF][row * 24 + (S) * 8 + 2 * cA];  \
            ahi[mt] = *(const uint2*)&As[SBUF][(row + 8) * 24 + (S) * 8 + 2 * cA]; \
        }                                                                     \
        _Pragma("unroll")                                                     \
        for (int nt = 0; nt < 4; nt++)                                        \
            bv[nt] = *(const uint2*)&Bs[SBUF][(wn0 + nt * 8 + gA) * 24 + (S) * 8 + 2 * cA]; \
        _Pragma("unroll")                                                     \
        for (int mt = 0; mt < 4; mt++)                                        \
            _Pragma("unroll")                                                 \
            for (int nt = 0; nt < 4; nt++)                                    \
                mma16(c[mt][nt], alo[mt], ahi[mt], bv[nt]);                   \
    } while (0)

// ---------------- conv 3x3: implicit GEMM, fp16 m16n8k16, double-buffered --
__global__ __launch_bounds__(256, 2) void k_conv(const float* __restrict__ bias) {
    __shared__ __align__(16) uint32_t As[2][128 * 24];
    __shared__ __align__(16) uint32_t Bs[2][128 * 24];
    int tid = threadIdx.x;
    int wid = tid >> 5, lane = tid & 31;
    int mbase = blockIdx.x * 128, nbase = blockIdx.y * 128;
    int wm0 = (wid >> 2) * 64, wn0 = (wid & 3) * 32;
    int gA = lane >> 2, cA = lane & 3;
    int r = tid >> 1, h = tid & 1;
    float c[4][4][4] = {};
    float4 z = make_float4(0.f, 0.f, 0.f, 0.f);

    // fill chunk 0: tap 0 (dy=-1,dx=-1), kc 0
    {
        int node = mbase + r;
        int hh = ((node >> 5) & 31) - 1, ww = (node & 31) - 1;
        bool ok = ((unsigned)hh < 32u) && ((unsigned)ww < 32u);
        const float4* ap = (const float4*)&g_bufA[(node - 33) * NC + h * 16];
        const float4* bp = (const float4*)&g_wt[(nbase + r) * NC + h * 16];
        sts_tile(As[0], r, h, ok ? ap[0] : z, ok ? ap[1] : z, ok ? ap[2] : z, ok ? ap[3] : z);
        sts_tile(Bs[0], r, h, bp[0], bp[1], bp[2], bp[3]);
    }
    __syncthreads();

    for (int ch = 0; ch < 72; ch++) {
        int cur = ch & 1, nxt = cur ^ 1;
        bool has = (ch + 1 < 72);
        float4 pa0, pa1, pa2, pa3, pb0, pb1, pb2, pb3;
        if (has) {
            int c1 = ch + 1;
            int tap = c1 >> 3, kc = c1 & 7;
            int dy = tap / 3 - 1, dx = tap % 3 - 1;
            int node = mbase + r;
            int hh = ((node >> 5) & 31) + dy, ww = (node & 31) + dx;
            bool ok = ((unsigned)hh < 32u) && ((unsigned)ww < 32u);
            const float4* ap = (const float4*)&g_bufA[(node + dy * 32 + dx) * NC + kc * 32 + h * 16];
            const float4* bp = (const float4*)&g_wt[(tap * NC + nbase + r) * NC + kc * 32 + h * 16];
            pa0 = ok ? ap[0] : z; pa1 = ok ? ap[1] : z;
            pa2 = ok ? ap[2] : z; pa3 = ok ? ap[3] : z;
            pb0 = bp[0]; pb1 = bp[1]; pb2 = bp[2]; pb3 = bp[3];
        }
        MMA_STEP(cur, 0);
        if (has) {
            sts_tile(As[nxt], r, h, pa0, pa1, pa2, pa3);
            sts_tile(Bs[nxt], r, h, pb0, pb1, pb2, pb3);
        }
        MMA_STEP(cur, 1);
        __syncthreads();
    }

    #pragma unroll
    for (int mt = 0; mt < 4; mt++) {
        #pragma unroll
        for (int nt = 0; nt < 4; nt++) {
            int row = mbase + wm0 + mt * 16 + gA;
            int col = nbase + wn0 + nt * 8 + 2 * cA;
            float b0 = bias[col], b1 = bias[col + 1];
            *(float2*)&g_bufB[row * NC + col] =
                make_float2(c[mt][nt][0] + b0, c[mt][nt][1] + b1);
            *(float2*)&g_bufB[(row + 8) * NC + col] =
                make_float2(c[mt][nt][2] + b0, c[mt][nt][3] + b1);
        }
    }
}

// ---------------- per-channel sum/sumsq over g_bufB ----------------
__global__ void k_stats(int so) {
    int c = threadIdx.x;
    int r0 = blockIdx.x * 64;
    float s = 0.f, ss = 0.f;
    #pragma unroll 4
    for (int r = 0; r < 64; r++) {
        float v = g_bufB[(r0 + r) * NC + c];
        s += v;
        ss += v * v;
    }
    atomicAdd(&g_stats[so + c], s);
    atomicAdd(&g_stats[so + 256 + c], ss);
}

__global__ void k_coef(int so, const float* __restrict__ gamma,
                       const float* __restrict__ beta, int co) {
    int c = threadIdx.x;
    float mean = g_stats[so + c] * (1.f / NNODES);
    float var  = g_stats[so + 256 + c] * (1.f / NNODES) - mean * mean;
    float sc = gamma[c] * rsqrtf(var + 1e-5f);
    g_coef[co + c] = sc;
    g_coef[co + 256 + c] = beta[c] - mean * sc;
}

// ---------------- bn2d+relu -> nodes ; zero agg ----------------
__global__ void k_bnrelu_zero() {
    int idx = blockIdx.x * 256 + threadIdx.x;
    int c4 = idx & 63;
    float4 v  = ((const float4*)g_bufB)[idx];
    float4 sc = ((const float4*)g_coef)[c4];
    float4 sh = ((const float4*)(g_coef + 256))[c4];
    v.x = fmaxf(fmaf(v.x, sc.x, sh.x), 0.f);
    v.y = fmaxf(fmaf(v.y, sc.y, sh.y), 0.f);
    v.z = fmaxf(fmaf(v.z, sc.z, sh.z), 0.f);
    v.w = fmaxf(fmaf(v.w, sc.w, sh.w), 0.f);
    ((float4*)g_nodes)[idx] = v;
    ((float4*)g_bufA)[idx] = make_float4(0.f, 0.f, 0.f, 0.f);
}

// ---------------- edge scatter-add: agg[dst] += nodes[src] ----------------
__global__ void k_scatter(const void* __restrict__ ei, int E) {
    int e = blockIdx.x * 8 + (threadIdx.x >> 5);
    if (e >= E) return;
    int lane = threadIdx.x & 31;
    int src, dst;
    if (g_is32) {
        const int* p = (const int*)ei;
        src = p[e]; dst = p[E + e];
    } else {
        const long long* p = (const long long*)ei;
        src = (int)p[e]; dst = (int)p[E + e];
    }
    const float4* sp = (const float4*)&g_nodes[src * NC];
    float4* dp = (float4*)&g_bufA[dst * NC];
    #pragma unroll
    for (int i = 0; i < 2; i++) {
        float4 v = sp[lane + i * 32];
        float4* p4 = dp + lane + i * 32;
        asm volatile("red.global.add.v4.f32 [%0], {%1,%2,%3,%4};"
                     :: "l"(p4), "f"(v.x), "f"(v.y), "f"(v.z), "f"(v.w)
                     : "memory");
    }
}

// ---------------- graph GEMM: g = [agg|nodes] @ [wrel|wroot]^T + b_rel ------
__global__ __launch_bounds__(256, 2) void k_gemm(const float* __restrict__ wrel,
                                                 const float* __restrict__ wroot,
                                                 const float* __restrict__ brel) {
    __shared__ __align__(16) uint32_t As[2][128 * 24];
    __shared__ __align__(16) uint32_t Bs[2][128 * 24];
    int tid = threadIdx.x;
    int wid = tid >> 5, lane = tid & 31;
    int mbase = blockIdx.x * 128, nbase = blockIdx.y * 128;
    int wm0 = (wid >> 2) * 64, wn0 = (wid & 3) * 32;
    int gA = lane >> 2, cA = lane & 3;
    int r = tid >> 1, h = tid & 1;
    float c[4][4][4] = {};

    // fill chunk 0 (agg, wrel, coff 0)
    {
        const float4* ap = (const float4*)&g_bufA[(mbase + r) * NC + h * 16];
        const float4* bp = (const float4*)&wrel[(nbase + r) * NC + h * 16];
        sts_tile(As[0], r, h, ap[0], ap[1], ap[2], ap[3]);
        sts_tile(Bs[0], r, h, bp[0], bp[1], bp[2], bp[3]);
    }
    __syncthreads();

    for (int ch = 0; ch < 16; ch++) {
        int cur = ch & 1, nxt = cur ^ 1;
        bool has = (ch + 1 < 16);
        float4 pa0, pa1, pa2, pa3, pb0, pb1, pb2, pb3;
        if (has) {
            int c1 = ch + 1;
            const float* ab = (c1 < 8) ? g_bufA : g_nodes;
            const float* bb = (c1 < 8) ? wrel : wroot;
            int coff = (c1 & 7) * 32;
            const float4* ap = (const float4*)&ab[(mbase + r) * NC + coff + h * 16];
            const float4* bp = (const float4*)&bb[(nbase + r) * NC + coff + h * 16];
            pa0 = ap[0]; pa1 = ap[1]; pa2 = ap[2]; pa3 = ap[3];
            pb0 = bp[0]; pb1 = bp[1]; pb2 = bp[2]; pb3 = bp[3];
        }
        MMA_STEP(cur, 0);
        if (has) {
            sts_tile(As[nxt], r, h, pa0, pa1, pa2, pa3);
            sts_tile(Bs[nxt], r, h, pb0, pb1, pb2, pb3);
        }
        MMA_STEP(cur, 1);
        __syncthreads();
    }

    #pragma unroll
    for (int mt = 0; mt < 4; mt++) {
        #pragma unroll
        for (int nt = 0; nt < 4; nt++) {
            int row = mbase + wm0 + mt * 16 + gA;
            int col = nbase + wn0 + nt * 8 + 2 * cA;
            float b0 = brel[col], b1 = brel[col + 1];
            *(float2*)&g_bufB[row * NC + col] =
                make_float2(c[mt][nt][0] + b0, c[mt][nt][1] + b1);
            *(float2*)&g_bufB[(row + 8) * NC + col] =
                make_float2(c[mt][nt][2] + b0, c[mt][nt][3] + b1);
        }
    }
}

// ---------------- bn1d+relu, transpose back to NCHW, residual ----------------
__global__ void k_final(const float* __restrict__ x, float* __restrict__ out) {
    __shared__ float tile[32 * 257];
    int bh = blockIdx.x;
    int b = bh >> 5, h = bh & 31;
    int nb = bh * 32;
    for (int i = threadIdx.x; i < 8192; i += 256) {
        int w = i >> 8, c = i & 255;
        tile[w * 257 + c] = g_bufB[(nb + w) * NC + c];
    }
    __syncthreads();
    for (int i = threadIdx.x; i < 8192; i += 256) {
        int c = i >> 5, w = i & 31;
        float v = fmaf(tile[w * 257 + c], g_coef[512 + c], g_coef[768 + c]);
        v = fmaxf(v, 0.f);
        int o = ((b * NC + c) * 32 + h) * 32 + w;
        out[o] = v + x[o];
    }
}

extern "C" void kernel_launch(void* const* d_in, const int* in_sizes, int n_in,
                              void* d_out, int out_size) {
    const float* x      = (const float*)d_in[0];
    const void*  ei     = d_in[1];
    const float* conv_w = (const float*)d_in[2];
    const float* conv_b = (const float*)d_in[3];
    const float* bn2d_g = (const float*)d_in[4];
    const float* bn2d_b = (const float*)d_in[5];
    const float* w_rel  = (const float*)d_in[6];
    const float* b_rel  = (const float*)d_in[7];
    const float* w_root = (const float*)d_in[8];
    const float* bn1d_g = (const float*)d_in[9];
    const float* bn1d_b = (const float*)d_in[10];
    float* out = (float*)d_out;
    int E = in_sizes[1] / 2;

    k_transpose_x<<<2048, 256>>>(x);
    k_prep<<<2304, 256>>>(conv_w);
    k_detect<<<1, 256>>>((const int*)ei);
    k_conv<<<dim3(512, 2), 256>>>(conv_b);
    k_stats<<<1024, 256>>>(0);
    k_coef<<<1, 256>>>(0, bn2d_g, bn2d_b, 0);
    k_bnrelu_zero<<<16384, 256>>>();
    k_scatter<<<(E + 7) / 8, 256>>>(ei, E);
    k_gemm<<<dim3(512, 2), 256>>>(w_rel, w_root, b_rel);
    k_stats<<<1024, 256>>>(512);
    k_coef<<<1, 256>>>(512, bn1d_g, bn1d_b, 512);
    k_final<<<2048, 256>>>(x, out);
}

// round 13
// speedup vs baseline: 3.3410x; 1.1957x over previous
#include <cuda_runtime.h>
#include <cuda_fp16.h>
#include <cstdint>

#define NNODES 65536
#define NC 256

typedef unsigned long long u64;

// Persistent scratch (no allocations allowed)
__device__ float g_bufA[NNODES * NC];       // agg (fp32, atomics)
__device__ float g_bufB[NNODES * NC];       // conv_out -> later g
__device__ float g_nodes[NNODES * NC];      // bn2d+relu node features (fp32 for scatter)
__device__ uint32_t g_xh[NNODES * 128];     // xt packed half (permuted)
__device__ uint32_t g_wth[9 * 256 * 128];   // conv weights packed half [tap][co][...]
__device__ uint32_t g_nodesh[NNODES * 128]; // nodes packed half
__device__ uint32_t g_aggh[NNODES * 128];   // agg packed half
__device__ uint32_t g_wch[16 * 256 * 16];   // [wrel|wroot] packed half [chunk][co][...]
__device__ float g_stats[1024];
__device__ float g_coef[1024];
__device__ int   g_is32;

__device__ __forceinline__ uint32_t h2u(float x, float y) {
    __half2 h = __floats2half2_rn(x, y);
    return *(uint32_t*)&h;
}
// permuted pack of 16 consecutive channels: q[2j]={f2j,f2j+1}, q[2j+1]={f8+2j,f9+2j}
__device__ __forceinline__ void pack16(uint32_t* q, const float* f) {
    #pragma unroll
    for (int j = 0; j < 4; j++) {
        q[2 * j]     = h2u(f[2 * j], f[2 * j + 1]);
        q[2 * j + 1] = h2u(f[8 + 2 * j], f[9 + 2 * j]);
    }
}
__device__ __forceinline__ void mma16(float* c, uint2 alo, uint2 ahi, uint2 b) {
    asm volatile(
        "mma.sync.aligned.m16n8k16.row.col.f32.f16.f16.f32 "
        "{%0,%1,%2,%3}, {%4,%5,%6,%7}, {%8,%9}, {%0,%1,%2,%3};"
        : "+f"(c[0]), "+f"(c[1]), "+f"(c[2]), "+f"(c[3])
        : "r"(alo.x), "r"(ahi.x), "r"(alo.y), "r"(ahi.y), "r"(b.x), "r"(b.y));
}

// ---------------- transpose x: NCHW -> packed half node-major ----------------
__global__ void k_transpose_x(const float* __restrict__ x) {
    __shared__ float tile[256 * 33];
    int bh = blockIdx.x;
    int b = bh >> 5, h = bh & 31;
    for (int i = threadIdx.x; i < 8192; i += 256) {
        int c = i >> 5, w = i & 31;
        tile[c * 33 + w] = x[((b * NC + c) * 32 + h) * 32 + w];
    }
    __syncthreads();
    int nb = bh * 32;
    for (int i = threadIdx.x; i < 512; i += 256) {
        int w = i >> 4, g = i & 15, kc = g >> 1, hh = g & 1;
        float f[16];
        #pragma unroll
        for (int j = 0; j < 16; j++) f[j] = tile[(kc * 32 + hh * 16 + j) * 33 + w];
        uint32_t q[8];
        pack16(q, f);
        uint4* dst = (uint4*)&g_xh[(nb + w) * 128 + kc * 16 + hh * 8];
        dst[0] = ((uint4*)q)[0];
        dst[1] = ((uint4*)q)[1];
    }
}

// ---------------- weight prep: pack conv & graph weights + zero stats --------
__global__ void k_prep(const float* __restrict__ cw,
                       const float* __restrict__ wrel,
                       const float* __restrict__ wroot) {
    int i = blockIdx.x * 256 + threadIdx.x;
    if (i < 36864) {   // conv: tap(9) x co(256) x kc(8) x h(2)
        int h = i & 1, kc = (i >> 1) & 7, co = (i >> 4) & 255, tap = i >> 12;
        float f[16];
        #pragma unroll
        for (int j = 0; j < 16; j++)
            f[j] = cw[(co * 256 + kc * 32 + h * 16 + j) * 9 + tap];
        uint32_t q[8];
        pack16(q, f);
        uint4* dst = (uint4*)&g_wth[(tap * 256 + co) * 128 + kc * 16 + h * 8];
        dst[0] = ((uint4*)q)[0];
        dst[1] = ((uint4*)q)[1];
    } else if (i < 45056) {   // graph: chunk(16) x co(256) x h(2)
        int t = i - 36864;
        int h = t & 1, co = (t >> 1) & 255, chc = t >> 9;
        const float* src = (chc < 8) ? wrel : wroot;
        float f[16];
        #pragma unroll
        for (int j = 0; j < 16; j++)
            f[j] = src[co * 256 + (chc & 7) * 32 + h * 16 + j];
        uint32_t q[8];
        pack16(q, f);
        uint4* dst = (uint4*)&g_wch[(chc * 256 + co) * 16 + h * 8];
        dst[0] = ((uint4*)q)[0];
        dst[1] = ((uint4*)q)[1];
    }
    if (blockIdx.x == 0) {
        for (int j = threadIdx.x; j < 1024; j += 256) g_stats[j] = 0.f;
    }
}

// ---------------- edge dtype detection ----------------
__global__ void k_detect(const int* __restrict__ ei32) {
    __shared__ int any;
    if (threadIdx.x == 0) any = 0;
    __syncthreads();
    int a = 0;
    for (int j = threadIdx.x; j < 8192; j += 256) a |= ei32[2 * j + 1];
    if (a) atomicOr(&any, 1);
    __syncthreads();
    if (threadIdx.x == 0) g_is32 = (any != 0) ? 1 : 0;
}

#define MMA_STEP(SBUF, S)                                                     \
    do {                                                                      \
        uint2 alo[4], ahi[4], bv[4];                                          \
        _Pragma("unroll")                                                     \
        for (int mt = 0; mt < 4; mt++) {                                      \
            int row = wm0 + mt * 16 + gA;                                     \
            alo[mt] = *(const uint2*)&As[SBUF][row * 24 + (S) * 8 + 2 * cA];  \
            ahi[mt] = *(const uint2*)&As[SBUF][(row + 8) * 24 + (S) * 8 + 2 * cA]; \
        }                                                                     \
        _Pragma("unroll")                                                     \
        for (int nt = 0; nt < 4; nt++)                                        \
            bv[nt] = *(const uint2*)&Bs[SBUF][(wn0 + nt * 8 + gA) * 24 + (S) * 8 + 2 * cA]; \
        _Pragma("unroll")                                                     \
        for (int mt = 0; mt < 4; mt++)                                        \
            _Pragma("unroll")                                                 \
            for (int nt = 0; nt < 4; nt++)                                    \
                mma16(c[mt][nt], alo[mt], ahi[mt], bv[nt]);                   \
    } while (0)

// ---------------- conv 3x3: implicit GEMM, fp16 m16n8k16, prepacked inputs --
__global__ __launch_bounds__(256, 2) void k_conv(const float* __restrict__ bias) {
    __shared__ __align__(16) uint32_t As[2][128 * 24];
    __shared__ __align__(16) uint32_t Bs[2][128 * 24];
    int tid = threadIdx.x;
    int wid = tid >> 5, lane = tid & 31;
    int mbase = blockIdx.x * 128, nbase = blockIdx.y * 128;
    int wm0 = (wid >> 2) * 64, wn0 = (wid & 3) * 32;
    int gA = lane >> 2, cA = lane & 3;
    int r = tid >> 1, h = tid & 1;
    float c[4][4][4] = {};
    uint4 z4 = make_uint4(0, 0, 0, 0);

    // fill chunk 0: tap 0 (dy=-1,dx=-1), kc 0
    {
        int node = mbase + r;
        int hh = ((node >> 5) & 31) - 1, ww = (node & 31) - 1;
        bool ok = ((unsigned)hh < 32u) && ((unsigned)ww < 32u);
        const uint4* ap = (const uint4*)&g_xh[(node - 33) * 128 + h * 8];
        const uint4* bp = (const uint4*)&g_wth[(nbase + r) * 128 + h * 8];
        uint32_t* qa = &As[0][r * 24 + h * 8];
        uint32_t* qb = &Bs[0][r * 24 + h * 8];
        *(uint4*)qa = ok ? ap[0] : z4;
        *(uint4*)(qa + 4) = ok ? ap[1] : z4;
        *(uint4*)qb = bp[0];
        *(uint4*)(qb + 4) = bp[1];
    }
    __syncthreads();

    for (int ch = 0; ch < 72; ch++) {
        int cur = ch & 1, nxt = cur ^ 1;
        bool has = (ch + 1 < 72);
        uint4 pa0, pa1, pb0, pb1;
        if (has) {
            int c1 = ch + 1;
            int tap = c1 >> 3, kc = c1 & 7;
            int dy = tap / 3 - 1, dx = tap % 3 - 1;
            int node = mbase + r;
            int hh = ((node >> 5) & 31) + dy, ww = (node & 31) + dx;
            bool ok = ((unsigned)hh < 32u) && ((unsigned)ww < 32u);
            const uint4* ap = (const uint4*)&g_xh[(node + dy * 32 + dx) * 128 + kc * 16 + h * 8];
            const uint4* bp = (const uint4*)&g_wth[(tap * 256 + nbase + r) * 128 + kc * 16 + h * 8];
            pa0 = ok ? ap[0] : z4;
            pa1 = ok ? ap[1] : z4;
            pb0 = bp[0];
            pb1 = bp[1];
        }
        MMA_STEP(cur, 0);
        if (has) {
            uint32_t* qa = &As[nxt][r * 24 + h * 8];
            uint32_t* qb = &Bs[nxt][r * 24 + h * 8];
            *(uint4*)qa = pa0;
            *(uint4*)(qa + 4) = pa1;
            *(uint4*)qb = pb0;
            *(uint4*)(qb + 4) = pb1;
        }
        MMA_STEP(cur, 1);
        __syncthreads();
    }

    #pragma unroll
    for (int mt = 0; mt < 4; mt++) {
        #pragma unroll
        for (int nt = 0; nt < 4; nt++) {
            int row = mbase + wm0 + mt * 16 + gA;
            int col = nbase + wn0 + nt * 8 + 2 * cA;
            float b0 = bias[col], b1 = bias[col + 1];
            *(float2*)&g_bufB[row * NC + col] =
                make_float2(c[mt][nt][0] + b0, c[mt][nt][1] + b1);
            *(float2*)&g_bufB[(row + 8) * NC + col] =
                make_float2(c[mt][nt][2] + b0, c[mt][nt][3] + b1);
        }
    }
}

// ---------------- per-channel sum/sumsq over g_bufB ----------------
__global__ void k_stats(int so) {
    int c = threadIdx.x;
    int r0 = blockIdx.x * 64;
    float s = 0.f, ss = 0.f;
    #pragma unroll 4
    for (int r = 0; r < 64; r++) {
        float v = g_bufB[(r0 + r) * NC + c];
        s += v;
        ss += v * v;
    }
    atomicAdd(&g_stats[so + c], s);
    atomicAdd(&g_stats[so + 256 + c], ss);
}

__global__ void k_coef(int so, const float* __restrict__ gamma,
                       const float* __restrict__ beta, int co) {
    int c = threadIdx.x;
    float mean = g_stats[so + c] * (1.f / NNODES);
    float var  = g_stats[so + 256 + c] * (1.f / NNODES) - mean * mean;
    float sc = gamma[c] * rsqrtf(var + 1e-5f);
    g_coef[co + c] = sc;
    g_coef[co + 256 + c] = beta[c] - mean * sc;
}

// ---------------- bn2d+relu -> nodes (fp32 + packed half) ; zero agg --------
__global__ void k_bnrelu_zero() {
    int i = blockIdx.x * 256 + threadIdx.x;   // 1048576 items
    int node = i >> 4, g = i & 15;
    int base = node * NC + g * 16;
    float f[16];
    float4 zz = make_float4(0.f, 0.f, 0.f, 0.f);
    #pragma unroll
    for (int j4 = 0; j4 < 4; j4++) {
        float4 v  = *(const float4*)&g_bufB[base + j4 * 4];
        float4 sc = *(const float4*)&g_coef[g * 16 + j4 * 4];
        float4 sh = *(const float4*)&g_coef[256 + g * 16 + j4 * 4];
        v.x = fmaxf(fmaf(v.x, sc.x, sh.x), 0.f);
        v.y = fmaxf(fmaf(v.y, sc.y, sh.y), 0.f);
        v.z = fmaxf(fmaf(v.z, sc.z, sh.z), 0.f);
        v.w = fmaxf(fmaf(v.w, sc.w, sh.w), 0.f);
        *(float4*)&g_nodes[base + j4 * 4] = v;
        *(float4*)&g_bufA[base + j4 * 4] = zz;
        f[j4 * 4 + 0] = v.x; f[j4 * 4 + 1] = v.y;
        f[j4 * 4 + 2] = v.z; f[j4 * 4 + 3] = v.w;
    }
    uint32_t q[8];
    pack16(q, f);
    uint4* dst = (uint4*)&g_nodesh[node * 128 + g * 8];
    dst[0] = ((uint4*)q)[0];
    dst[1] = ((uint4*)q)[1];
}

// ---------------- edge scatter-add: agg[dst] += nodes[src] ----------------
__global__ void k_scatter(const void* __restrict__ ei, int E) {
    int e = blockIdx.x * 8 + (threadIdx.x >> 5);
    if (e >= E) return;
    int lane = threadIdx.x & 31;
    int src, dst;
    if (g_is32) {
        const int* p = (const int*)ei;
        src = p[e]; dst = p[E + e];
    } else {
        const long long* p = (const long long*)ei;
        src = (int)p[e]; dst = (int)p[E + e];
    }
    const float4* sp = (const float4*)&g_nodes[src * NC];
    float4* dp = (float4*)&g_bufA[dst * NC];
    #pragma unroll
    for (int i = 0; i < 2; i++) {
        float4 v = sp[lane + i * 32];
        float4* p4 = dp + lane + i * 32;
        asm volatile("red.global.add.v4.f32 [%0], {%1,%2,%3,%4};"
                     :: "l"(p4), "f"(v.x), "f"(v.y), "f"(v.z), "f"(v.w)
                     : "memory");
    }
}

// ---------------- pack agg fp32 -> half permuted ----------------
__global__ void k_cvt_agg() {
    int i = blockIdx.x * 256 + threadIdx.x;
    int node = i >> 4, g = i & 15;
    int base = node * NC + g * 16;
    float f[16];
    #pragma unroll
    for (int j4 = 0; j4 < 4; j4++) {
        float4 v = *(const float4*)&g_bufA[base + j4 * 4];
        f[j4 * 4 + 0] = v.x; f[j4 * 4 + 1] = v.y;
        f[j4 * 4 + 2] = v.z; f[j4 * 4 + 3] = v.w;
    }
    uint32_t q[8];
    pack16(q, f);
    uint4* dst = (uint4*)&g_aggh[node * 128 + g * 8];
    dst[0] = ((uint4*)q)[0];
    dst[1] = ((uint4*)q)[1];
}

// ---------------- graph GEMM: g = [agg|nodes] @ [wrel|wroot]^T + b_rel ------
__global__ __launch_bounds__(256, 2) void k_gemm(const float* __restrict__ brel) {
    __shared__ __align__(16) uint32_t As[2][128 * 24];
    __shared__ __align__(16) uint32_t Bs[2][128 * 24];
    int tid = threadIdx.x;
    int wid = tid >> 5, lane = tid & 31;
    int mbase = blockIdx.x * 128, nbase = blockIdx.y * 128;
    int wm0 = (wid >> 2) * 64, wn0 = (wid & 3) * 32;
    int gA = lane >> 2, cA = lane & 3;
    int r = tid >> 1, h = tid & 1;
    float c[4][4][4] = {};

    {
        const uint4* ap = (const uint4*)&g_aggh[(mbase + r) * 128 + h * 8];
        const uint4* bp = (const uint4*)&g_wch[(nbase + r) * 16 + h * 8];
        uint32_t* qa = &As[0][r * 24 + h * 8];
        uint32_t* qb = &Bs[0][r * 24 + h * 8];
        *(uint4*)qa = ap[0];
        *(uint4*)(qa + 4) = ap[1];
        *(uint4*)qb = bp[0];
        *(uint4*)(qb + 4) = bp[1];
    }
    __syncthreads();

    for (int ch = 0; ch < 16; ch++) {
        int cur = ch & 1, nxt = cur ^ 1;
        bool has = (ch + 1 < 16);
        uint4 pa0, pa1, pb0, pb1;
        if (has) {
            int c1 = ch + 1;
            const uint32_t* ab = (c1 < 8) ? g_aggh : g_nodesh;
            int kc = c1 & 7;
            const uint4* ap = (const uint4*)&ab[(mbase + r) * 128 + kc * 16 + h * 8];
            const uint4* bp = (const uint4*)&g_wch[(c1 * 256 + nbase + r) * 16 + h * 8];
            pa0 = ap[0]; pa1 = ap[1];
            pb0 = bp[0]; pb1 = bp[1];
        }
        MMA_STEP(cur, 0);
        if (has) {
            uint32_t* qa = &As[nxt][r * 24 + h * 8];
            uint32_t* qb = &Bs[nxt][r * 24 + h * 8];
            *(uint4*)qa = pa0;
            *(uint4*)(qa + 4) = pa1;
            *(uint4*)qb = pb0;
            *(uint4*)(qb + 4) = pb1;
        }
        MMA_STEP(cur, 1);
        __syncthreads();
    }

    #pragma unroll
    for (int mt = 0; mt < 4; mt++) {
        #pragma unroll
        for (int nt = 0; nt < 4; nt++) {
            int row = mbase + wm0 + mt * 16 + gA;
            int col = nbase + wn0 + nt * 8 + 2 * cA;
            float b0 = brel[col], b1 = brel[col + 1];
            *(float2*)&g_bufB[row * NC + col] =
                make_float2(c[mt][nt][0] + b0, c[mt][nt][1] + b1);
            *(float2*)&g_bufB[(row + 8) * NC + col] =
                make_float2(c[mt][nt][2] + b0, c[mt][nt][3] + b1);
        }
    }
}

// ---------------- bn1d+relu, transpose back to NCHW, residual ----------------
__global__ void k_final(const float* __restrict__ x, float* __restrict__ out) {
    __shared__ float tile[32 * 257];
    int bh = blockIdx.x;
    int b = bh >> 5, h = bh & 31;
    int nb = bh * 32;
    for (int i = threadIdx.x; i < 8192; i += 256) {
        int w = i >> 8, c = i & 255;
        tile[w * 257 + c] = g_bufB[(nb + w) * NC + c];
    }
    __syncthreads();
    for (int i = threadIdx.x; i < 8192; i += 256) {
        int c = i >> 5, w = i & 31;
        float v = fmaf(tile[w * 257 + c], g_coef[512 + c], g_coef[768 + c]);
        v = fmaxf(v, 0.f);
        int o = ((b * NC + c) * 32 + h) * 32 + w;
        out[o] = v + x[o];
    }
}

extern "C" void kernel_launch(void* const* d_in, const int* in_sizes, int n_in,
                              void* d_out, int out_size) {
    const float* x      = (const float*)d_in[0];
    const void*  ei     = d_in[1];
    const float* conv_w = (const float*)d_in[2];
    const float* conv_b = (const float*)d_in[3];
    const float* bn2d_g = (const float*)d_in[4];
    const float* bn2d_b = (const float*)d_in[5];
    const float* w_rel  = (const float*)d_in[6];
    const float* b_rel  = (const float*)d_in[7];
    const float* w_root = (const float*)d_in[8];
    const float* bn1d_g = (const float*)d_in[9];
    const float* bn1d_b = (const float*)d_in[10];
    float* out = (float*)d_out;
    int E = in_sizes[1] / 2;

    k_transpose_x<<<2048, 256>>>(x);
    k_prep<<<176, 256>>>(conv_w, w_rel, w_root);
    k_detect<<<1, 256>>>((const int*)ei);
    k_conv<<<dim3(512, 2), 256>>>(conv_b);
    k_stats<<<1024, 256>>>(0);
    k_coef<<<1, 256>>>(0, bn2d_g, bn2d_b, 0);
    k_bnrelu_zero<<<4096, 256>>>();
    k_scatter<<<(E + 7) / 8, 256>>>(ei, E);
    k_cvt_agg<<<4096, 256>>>();
    k_gemm<<<dim3(512, 2), 256>>>(b_rel);
    k_stats<<<1024, 256>>>(512);
    k_coef<<<1, 256>>>(512, bn1d_g, bn1d_b, 512);
    k_final<<<2048, 256>>>(x, out);
}